// round 13
// baseline (speedup 1.0000x reference)
#include <cuda_runtime.h>
#include <math_constants.h>

#define NST 1024
#define TT  4096
#define DD  20
#define NCTA 128

// ---------------- device scratch (no allocations allowed) ----------------
__device__ float g_LTT[NST * NST];        // 4 MB: LTT[j][k] = log(trans[k][j])
__device__ float g_M[DD * NST];           // mean          (layout [d][n])
__device__ float g_S[DD * NST];           // 2*s^2         (layout [d][n])
__device__ float g_C[DD * NST];           // (2*pi*s)^-0.5 (layout [d][n])
__device__ float g_E[TT * NST];           // 16 MB emissions E[t][n] (may be -inf)
__device__ unsigned short g_bp[TT * NST]; // 8 MB backpointers, rows t=1..T-1
__device__ float g_colA[NST];
__device__ float g_colB[NST];
__device__ int g_last;
__device__ unsigned g_arrive;             // monotonic barrier arrivals
__device__ unsigned g_release;            // monotonic barrier epochs

// ---------------- K1a: transposed log-transition ----------------
__global__ void k_ltt(const float* __restrict__ trans) {
    int k = blockIdx.x;
    for (int j = threadIdx.x; j < NST; j += 256)
        g_LTT[j * NST + k] = logf(trans[k * NST + j]);
}

// ---------------- K1b: emission parameter prep ----------------
__global__ void k_params(const float* __restrict__ ep) {
    int n = blockIdx.x;
    int d = threadIdx.x;  // 32 threads, d < 20 active
    if (d < DD) {
        float m = ep[(n * DD + d) * 2 + 0];
        float s = ep[(n * DD + d) * 2 + 1];
        g_M[d * NST + n] = m;
        g_S[d * NST + n] = 2.0f * (s * s);                       // 2*std^2
        g_C[d * NST + n] = 1.0f / sqrtf(2.0f * CUDART_PI_F * s); // (2*pi*std)^-0.5
    }
}

// ---------------- K2: emissions, exact reference form ----------------
// per dim: p = C * exp(-(x-m)^2 / (2 s^2));  logp = log(p)  (-inf kept on underflow)
__global__ void __launch_bounds__(256) k_emis(const float* __restrict__ ev) {
    int n = blockIdx.y * 256 + threadIdx.x;
    int t0 = blockIdx.x * 64;
    __shared__ float sx[64][DD];
    for (int i = threadIdx.x; i < 64 * DD; i += 256) {
        int tt = i / DD, dd = i % DD;
        sx[tt][dd] = ev[(t0 + tt) * DD + dd];
    }
    __syncthreads();
    float M[DD], S[DD], C[DD];
#pragma unroll
    for (int d = 0; d < DD; d++) {
        M[d] = g_M[d * NST + n];
        S[d] = g_S[d * NST + n];
        C[d] = g_C[d * NST + n];
    }
    for (int tt = 0; tt < 64; tt++) {
        float acc = 0.f;
#pragma unroll
        for (int d = 0; d < DD; d++) {
            float diff = sx[tt][d] - M[d];
            float p = C[d] * expf(-(diff * diff) / S[d]);
            acc += logf(p);
        }
        g_E[(t0 + tt) * NST + n] = acc;
    }
}

// ---------------- K3a: initial column ----------------
__global__ void k_init(const float* __restrict__ prior) {
    int j = blockIdx.x * 256 + threadIdx.x;
    g_colA[j] = logf(prior[j]) + g_E[j];   // col0 = log(prior) + logp0
}

// ---------------- K3b: persistent brute-force Viterbi forward ----------------
// 128 CTAs x 256 threads; warp owns column j; scores[k][j] = prev[k] + lt[k][j];
// first-max argmax (smallest k on ties, matching jnp.argmax).
// j==0: VALUE forced to prev[0]+lt[0][0]; bp stays the generic argmax
// (identical to the expression the reference backtrack recomputes).
__global__ void __launch_bounds__(256) k_forward() {
    int w = threadIdx.x >> 5, lane = threadIdx.x & 31;
    int j = blockIdx.x * 8 + w;
    const float* __restrict__ row = g_LTT + (size_t)j * NST;  // row[k] = lt[k][j]
    unsigned base = *(volatile unsigned*)&g_release;  // settled epoch from prior runs

    for (int step = 1; step < TT; step++) {
        const float* prev = (step & 1) ? g_colA : g_colB;
        float*       next = (step & 1) ? g_colB : g_colA;
        float e = g_E[step * NST + j];

        float bv = -CUDART_INF_F;
        int bk = 0;
#pragma unroll 8
        for (int i = 0; i < 32; i++) {
            int k = i * 32 + lane;                     // ascending per lane
            float v = __ldcg(&prev[k]) + row[k];
            if (v > bv) { bv = v; bk = k; }
        }
        for (int o = 16; o; o >>= 1) {
            float ov = __shfl_xor_sync(0xffffffffu, bv, o);
            int   ok = __shfl_xor_sync(0xffffffffu, bk, o);
            if (ov > bv || (ov == bv && ok < bk)) { bv = ov; bk = ok; }
        }
        if (lane == 0) {
            if (j == 0) bv = __ldcg(&prev[0]) + row[0];  // value override only
            __stcg(&next[j], bv + e);
            g_bp[step * NST + j] = (unsigned short)bk;
        }

        // ---- grid barrier (epoch counting, replay-safe) ----
        __threadfence();
        __syncthreads();
        if (threadIdx.x == 0) {
            unsigned target = base + (unsigned)step;
            unsigned arrived = atomicAdd(&g_arrive, 1u) + 1u;
            if (arrived == target * (unsigned)NCTA) {
                atomicExch(&g_release, target);
            } else {
                while (*(volatile unsigned*)&g_release < target) {}
            }
            __threadfence();
        }
        __syncthreads();
    }
}

// ---------------- K3c: final-column first-max argmax ----------------
__global__ void k_final() {
    const float* col = ((TT - 1) & 1) ? g_colB : g_colA;
    __shared__ float s_v[32];
    __shared__ int s_i[32];
    int t = threadIdx.x, lane = t & 31, w = t >> 5;
    float v = col[t];
    int idx = t;
    for (int o = 16; o; o >>= 1) {
        float ov = __shfl_xor_sync(0xffffffffu, v, o);
        int   oi = __shfl_xor_sync(0xffffffffu, idx, o);
        if (ov > v || (ov == v && oi < idx)) { v = ov; idx = oi; }
    }
    if (lane == 0) { s_v[w] = v; s_i[w] = idx; }
    __syncthreads();
    if (t == 0) {
        for (int i = 1; i < 32; i++)
            if (s_v[i] > v || (s_v[i] == v && s_i[i] < idx)) { v = s_v[i]; idx = s_i[i]; }
        g_last = idx;
    }
}

// ---------------- K4a: fill ENTIRE output buffer with `last` (as float) ----------
// Guards against out_size > T+1 (unwritten poison) and establishes float dtype.
__global__ void k_fill(float* __restrict__ out, int n) {
    int last = g_last;
    for (int i = blockIdx.x * 256 + threadIdx.x; i < n; i += gridDim.x * 256)
        out[i] = (float)last;
}

// ---------------- K4b: serial backtrack, FLOAT output ----------------
// sequence = [s_0 .. s_{T-2}, last, last]  written as float32 values
__global__ void k_backtrack(float* __restrict__ out) {
    int cur = g_last;
    out[TT] = (float)cur;
    out[TT - 1] = (float)cur;
    for (int i = TT - 2; i >= 0; i--) {
        cur = (int)g_bp[(i + 1) * NST + cur];
        out[i] = (float)cur;
    }
}

// ---------------- launch ----------------
extern "C" void kernel_launch(void* const* d_in, const int* in_sizes, int n_in,
                              void* d_out, int out_size) {
    // Bind inputs BY ELEMENT COUNT (all four counts are distinct):
    //   evidence [T,D]=81920, prior [N]=1024, trans [N,N]=1048576, emission [N,D,2]=40960
    const float* evidence = 0;
    const float* prior = 0;
    const float* trans = 0;
    const float* emis = 0;
    for (int i = 0; i < n_in; i++) {
        switch (in_sizes[i]) {
            case TT * DD:       evidence = (const float*)d_in[i]; break;
            case NST:           prior    = (const float*)d_in[i]; break;
            case NST * NST:     trans    = (const float*)d_in[i]; break;
            case NST * DD * 2:  emis     = (const float*)d_in[i]; break;
        }
    }
    float* out = (float*)d_out;

    k_ltt<<<NST, 256>>>(trans);
    k_params<<<NST, 32>>>(emis);
    k_emis<<<dim3(TT / 64, NST / 256), 256>>>(evidence);
    k_init<<<NST / 256, 256>>>(prior);
    k_forward<<<NCTA, 256>>>();
    k_final<<<1, 1024>>>();
    int n = out_size > 0 ? out_size : (TT + 1);
    k_fill<<<(n + 255) / 256 < 64 ? (n + 255) / 256 : 64, 256>>>(out, n);
    k_backtrack<<<1, 1>>>(out);
}

// round 15
// speedup vs baseline: 2.2339x; 2.2339x over previous
#include <cuda_runtime.h>
#include <math_constants.h>

#define NST 1024
#define TT  4096
#define DD  20

// ---------------- device scratch (no allocations allowed) ----------------
__device__ float g_LT[NST * NST];         // 4 MB  log(transition), row-major [k][j]
__device__ float g_rowmax[NST];
__device__ float g_rowmin[NST];
__device__ float g_M[DD * NST];           // mean          (layout [d][n])
__device__ float g_S[DD * NST];           // 2*s^2         (layout [d][n])
__device__ float g_C[DD * NST];           // (2*pi*s)^-0.5 (layout [d][n])
__device__ float g_E[TT * NST];           // 16 MB emissions E[t][n] (may be -inf)
__device__ unsigned short g_bp[TT * NST]; // 8 MB backpointers, rows t=1..T-1
__device__ int g_last;

// ---------------- K1a: log-transition + per-row min/max ----------------
__global__ void k_lt(const float* __restrict__ trans) {
    int k = blockIdx.x;
    int tid = threadIdx.x;
    float mx = -CUDART_INF_F, mn = CUDART_INF_F;
    for (int j = tid; j < NST; j += 256) {
        float v = logf(trans[k * NST + j]);
        g_LT[k * NST + j] = v;
        mx = fmaxf(mx, v);
        mn = fminf(mn, v);
    }
    for (int o = 16; o; o >>= 1) {
        mx = fmaxf(mx, __shfl_xor_sync(0xffffffffu, mx, o));
        mn = fminf(mn, __shfl_xor_sync(0xffffffffu, mn, o));
    }
    __shared__ float smx[8], smn[8];
    if ((tid & 31) == 0) { smx[tid >> 5] = mx; smn[tid >> 5] = mn; }
    __syncthreads();
    if (tid == 0) {
        for (int w = 1; w < 8; w++) { mx = fmaxf(mx, smx[w]); mn = fminf(mn, smn[w]); }
        g_rowmax[k] = mx;
        g_rowmin[k] = mn;
    }
}

// ---------------- K1b: emission parameter prep ----------------
__global__ void k_params(const float* __restrict__ ep) {
    int n = blockIdx.x;
    int d = threadIdx.x;  // 32 threads, d < 20 active
    if (d < DD) {
        float m = ep[(n * DD + d) * 2 + 0];
        float s = ep[(n * DD + d) * 2 + 1];
        g_M[d * NST + n] = m;
        g_S[d * NST + n] = 2.0f * (s * s);                       // 2*std^2
        g_C[d * NST + n] = 1.0f / sqrtf(2.0f * CUDART_PI_F * s); // (2*pi*std)^-0.5
    }
}

// ---------------- K2: emissions, exact reference form (PROVEN rel_err=0) ----------------
__global__ void __launch_bounds__(256) k_emis(const float* __restrict__ ev) {
    int n = blockIdx.y * 256 + threadIdx.x;
    int t0 = blockIdx.x * 64;
    __shared__ float sx[64][DD];
    for (int i = threadIdx.x; i < 64 * DD; i += 256) {
        int tt = i / DD, dd = i % DD;
        sx[tt][dd] = ev[(t0 + tt) * DD + dd];
    }
    __syncthreads();
    float M[DD], S[DD], C[DD];
#pragma unroll
    for (int d = 0; d < DD; d++) {
        M[d] = g_M[d * NST + n];
        S[d] = g_S[d * NST + n];
        C[d] = g_C[d * NST + n];
    }
    for (int tt = 0; tt < 64; tt++) {
        float acc = 0.f;
#pragma unroll
        for (int d = 0; d < DD; d++) {
            float diff = sx[tt][d] - M[d];
            float p = C[d] * expf(-(diff * diff) / S[d]);
            acc += logf(p);                 // -inf kept, like reference
        }
        g_E[(t0 + tt) * NST + n] = acc;
    }
}

// ---------------- K3: pruned Viterbi forward (single persistent CTA) ----------------
// Exact pruning: L = max_k(prev[k]+rowmin[k]) lower-bounds every column winner;
// any k with prev[k]+rowmax[k] < L can never be (or tie) a winner -> drop.
// Candidates kept in ascending k order => first-max (jnp.argmax) semantics.
__global__ void __launch_bounds__(1024, 1) k_viterbi(const float* __restrict__ prior) {
    __shared__ float prev[NST];       // 4 KB
    __shared__ float bests[4][NST];   // 16 KB
    __shared__ int   args[4][NST];    // 16 KB
    __shared__ int   cand[NST];       // 4 KB
    __shared__ float s_red[32];
    __shared__ int   s_cnt[32];
    __shared__ float s_L;
    __shared__ int   s_C;
    __shared__ float s_rv[32];
    __shared__ int   s_ri[32];

    int t = threadIdx.x;
    int wid = t >> 5, lane = t & 31;
    int q = t >> 8;          // candidate sub-group 0..3
    int u = t & 255;         // owns columns 4u..4u+3 in the main loop

    float rmin = g_rowmin[t];
    float rmax = g_rowmax[t];
    float pv0 = logf(prior[t]) + g_E[t];   // col0 = log(prior) + logp0
    prev[t] = pv0;
    float LT00 = g_LT[0];
    float prev0 = pv0;                     // only thread 0's copy is used
    __syncthreads();

    const float4* LT4 = reinterpret_cast<const float4*>(g_LT);

    for (int step = 1; step < TT; step++) {
        float e = g_E[step * NST + t];     // prefetch emission for column t

        // L = max_k (prev[k] + rowmin[k])
        float pk = prev[t];
        float sm = pk + rmin;
        for (int o = 16; o; o >>= 1) sm = fmaxf(sm, __shfl_xor_sync(0xffffffffu, sm, o));
        if (lane == 0) s_red[wid] = sm;
        __syncthreads();
        if (wid == 0) {
            float v = s_red[lane];
            for (int o = 16; o; o >>= 1) v = fmaxf(v, __shfl_xor_sync(0xffffffffu, v, o));
            if (lane == 0) s_L = v;
        }
        __syncthreads();
        float L = s_L;

        // candidate compaction (ascending k preserved)
        bool pred = (pk + rmax) >= L;
        unsigned mask = __ballot_sync(0xffffffffu, pred);
        if (lane == 0) s_cnt[wid] = __popc(mask);
        __syncthreads();
        if (wid == 0) {
            int c = s_cnt[lane];
            int x = c;
            for (int o = 1; o < 32; o <<= 1) {
                int y = __shfl_up_sync(0xffffffffu, x, o);
                if (lane >= o) x += y;
            }
            s_cnt[lane] = x - c;           // exclusive prefix
            if (lane == 31) s_C = x;
        }
        __syncthreads();
        if (pred) {
            int pos = s_cnt[wid] + __popc(mask & ((1u << lane) - 1u));
            cand[pos] = t;
        }
        __syncthreads();
        int C = s_C;

        // main max-plus over candidates; 4 groups, 4 columns/thread
        float4 b = make_float4(-CUDART_INF_F, -CUDART_INF_F, -CUDART_INF_F, -CUDART_INF_F);
        int4 a = make_int4(0, 0, 0, 0);
        for (int c = q; c < C; c += 4) {
            int k = cand[c];
            float pvk = prev[k];
            float4 f = LT4[k * (NST / 4) + u];
            float v0 = pvk + f.x; if (v0 > b.x) { b.x = v0; a.x = k; }
            float v1 = pvk + f.y; if (v1 > b.y) { b.y = v1; a.y = k; }
            float v2 = pvk + f.z; if (v2 > b.z) { b.z = v2; a.z = k; }
            float v3 = pvk + f.w; if (v3 > b.w) { b.w = v3; a.w = k; }
        }
        bests[q][4 * u + 0] = b.x; args[q][4 * u + 0] = a.x;
        bests[q][4 * u + 1] = b.y; args[q][4 * u + 1] = a.y;
        bests[q][4 * u + 2] = b.z; args[q][4 * u + 2] = a.z;
        bests[q][4 * u + 3] = b.w; args[q][4 * u + 3] = a.w;
        __syncthreads();

        // combine groups (first-max: smaller k wins ties)
        float bv = bests[0][t]; int ba = args[0][t];
#pragma unroll
        for (int g2 = 1; g2 < 4; g2++) {
            float v = bests[g2][t]; int aa = args[g2][t];
            if (v > bv || (v == bv && aa < ba)) { bv = v; ba = aa; }
        }
        // j==0 VALUE override (bp stays the generic argmax, matching backtrack)
        if (t == 0) bv = prev0 + LT00;
        float nv = bv + e;
        g_bp[step * NST + t] = (unsigned short)ba;
        __syncthreads();
        prev[t] = nv;
        if (t == 0) prev0 = nv;
        __syncthreads();
    }

    // final column first-max argmax
    float v = prev[t];
    int idx = t;
    for (int o = 16; o; o >>= 1) {
        float ov = __shfl_xor_sync(0xffffffffu, v, o);
        int oi = __shfl_xor_sync(0xffffffffu, idx, o);
        if (ov > v || (ov == v && oi < idx)) { v = ov; idx = oi; }
    }
    if (lane == 0) { s_rv[wid] = v; s_ri[wid] = idx; }
    __syncthreads();
    if (t == 0) {
        for (int w = 1; w < 32; w++) {
            if (s_rv[w] > v || (s_rv[w] == v && s_ri[w] < idx)) { v = s_rv[w]; idx = s_ri[w]; }
        }
        g_last = idx;
    }
}

// ---------------- K4a: fill ENTIRE output buffer with `last` (float) ----------------
__global__ void k_fill(float* __restrict__ out, int n) {
    int last = g_last;
    for (int i = blockIdx.x * 256 + threadIdx.x; i < n; i += gridDim.x * 256)
        out[i] = (float)last;
}

// ---------------- K4b: serial backtrack, FLOAT output ----------------
// sequence = [s_0 .. s_{T-2}, last, last]
__global__ void k_backtrack(float* __restrict__ out) {
    int cur = g_last;
    out[TT] = (float)cur;
    out[TT - 1] = (float)cur;
    for (int i = TT - 2; i >= 0; i--) {
        cur = (int)g_bp[(i + 1) * NST + cur];
        out[i] = (float)cur;
    }
}

// ---------------- launch ----------------
extern "C" void kernel_launch(void* const* d_in, const int* in_sizes, int n_in,
                              void* d_out, int out_size) {
    // Bind inputs BY ELEMENT COUNT (all four counts distinct):
    //   evidence [T,D]=81920, prior [N]=1024, trans [N,N]=1048576, emission [N,D,2]=40960
    const float* evidence = 0;
    const float* prior = 0;
    const float* trans = 0;
    const float* emis = 0;
    for (int i = 0; i < n_in; i++) {
        switch (in_sizes[i]) {
            case TT * DD:       evidence = (const float*)d_in[i]; break;
            case NST:           prior    = (const float*)d_in[i]; break;
            case NST * NST:     trans    = (const float*)d_in[i]; break;
            case NST * DD * 2:  emis     = (const float*)d_in[i]; break;
        }
    }
    float* out = (float*)d_out;

    k_lt<<<NST, 256>>>(trans);
    k_params<<<NST, 32>>>(emis);
    k_emis<<<dim3(TT / 64, NST / 256), 256>>>(evidence);
    k_viterbi<<<1, 1024>>>(prior);
    int n = out_size > 0 ? out_size : (TT + 1);
    int g = (n + 255) / 256; if (g > 64) g = 64;
    k_fill<<<g, 256>>>(out, n);
    k_backtrack<<<1, 1>>>(out);
}